// round 1
// baseline (speedup 1.0000x reference)
#include <cuda_runtime.h>
#include <cstdint>

// TransitionLayer: BN(eval) + ReLU + 1x1 conv (512->256) + avgpool2x2, NCHW fp32.
// Identity used: avgpool(conv1x1(act)) == conv1x1(avgpool(act))  (conv linear, pointwise in space)
// => GEMM: M = 64*28*28 = 50176 pooled pixels, K = 512, N = 256.  13.15 GFLOP.
// Packed fp32 FMA (fma.rn.f32x2 -> FFMA2) for 2x fp32 throughput on sm_103a.

#define BN_EPS 1e-5f

constexpr int NIMG = 64;
constexpr int CIN  = 512;
constexpr int HH   = 56;
constexpr int WW   = 56;
constexpr int COUT = 256;
constexpr int PP   = 28;              // pooled H/W
constexpr int PIX  = PP * PP;         // 784 pooled pixels per image
constexpr int M_TOTAL = NIMG * PIX;   // 50176

constexpr int BM = 64;                // pooled pixels per block
constexpr int BK = 16;                // channels per k-tile
constexpr int BSROW = 258;            // padded Bs row (conflict-free stores, 8B-aligned reads)

__global__ __launch_bounds__(256, 2)
void transition_fused_kernel(const float* __restrict__ x,
                             const float* __restrict__ bn_w,
                             const float* __restrict__ bn_b,
                             const float* __restrict__ bn_m,
                             const float* __restrict__ bn_v,
                             const float* __restrict__ conv_w,
                             float* __restrict__ out)
{
    __shared__ float s_scale[CIN];
    __shared__ float s_shift[CIN];
    __shared__ __align__(16) float As[BK][BM];
    __shared__ __align__(16) float Bs[BK][BSROW];

    const int tid = threadIdx.x;

    // Per-channel BN scale/shift (once per block; 512 ch / 256 thr = 2 each)
    for (int c = tid; c < CIN; c += 256) {
        float inv = rsqrtf(bn_v[c] + BN_EPS);
        float sc  = bn_w[c] * inv;
        s_scale[c] = sc;
        s_shift[c] = bn_b[c] - bn_m[c] * sc;
    }

    const int m0 = blockIdx.x * BM;

    // Compute-phase thread mapping: lanes vary along m (coalesced epilogue).
    const int tm = tid & 31;      // m-lane: handles m0+tm and m0+tm+32
    const int tn = tid >> 5;      // n-group 0..7: outputs [tn*32, tn*32+32)

    // A-load mapping: ml = pooled pixel within tile, ks = k phase
    const int ml = tid & 63;
    const int ks = tid >> 6;      // 0..3
    {
        // nothing
    }
    const int m_load   = m0 + ml;
    const int nimg_l   = m_load / PIX;
    const int pix_l    = m_load % PIX;
    const int pi       = pix_l / PP;
    const int pj       = pix_l % PP;
    const float* xbase = x + ((size_t)(nimg_l * CIN) * HH + 2 * pi) * WW + 2 * pj;

    unsigned long long acc[2][16];
    #pragma unroll
    for (int i = 0; i < 2; i++)
        #pragma unroll
        for (int p = 0; p < 16; p++) acc[i][p] = 0ULL;

    __syncthreads();   // s_scale/s_shift ready

    for (int c0 = 0; c0 < CIN; c0 += BK) {
        // ---- Load A tile: pooled ReLU(BN(x)) for BM pixels x BK channels ----
        #pragma unroll
        for (int kk = 0; kk < BK; kk += 4) {
            const int k = kk + ks;
            const int c = c0 + k;
            const float* xp = xbase + (size_t)c * (HH * WW);
            float2 r0 = *reinterpret_cast<const float2*>(xp);
            float2 r1 = *reinterpret_cast<const float2*>(xp + WW);
            float sc = s_scale[c], sh = s_shift[c];
            float v = fmaxf(fmaf(r0.x, sc, sh), 0.0f)
                    + fmaxf(fmaf(r0.y, sc, sh), 0.0f)
                    + fmaxf(fmaf(r1.x, sc, sh), 0.0f)
                    + fmaxf(fmaf(r1.y, sc, sh), 0.0f);
            As[k][ml] = 0.25f * v;
        }
        // ---- Load B tile: Bs[k][o] = W[o][c0+k], float4 global reads ----
        {
            const int olane = tid >> 2;            // 0..63
            const int kq    = (tid & 3) * 4;       // 0,4,8,12
            #pragma unroll
            for (int pass = 0; pass < 4; pass++) {
                const int o = pass * 64 + olane;
                float4 v = *reinterpret_cast<const float4*>(conv_w + (size_t)o * CIN + c0 + kq);
                Bs[kq + 0][o] = v.x;
                Bs[kq + 1][o] = v.y;
                Bs[kq + 2][o] = v.z;
                Bs[kq + 3][o] = v.w;
            }
        }
        __syncthreads();

        // ---- FFMA2 inner product ----
        #pragma unroll
        for (int k = 0; k < BK; k++) {
            float a0 = As[k][tm];
            float a1 = As[k][tm + 32];
            unsigned long long A0, A1;
            unsigned int a0u = __float_as_uint(a0);
            unsigned int a1u = __float_as_uint(a1);
            asm("mov.b64 %0, {%1,%2};" : "=l"(A0) : "r"(a0u), "r"(a0u));
            asm("mov.b64 %0, {%1,%2};" : "=l"(A1) : "r"(a1u), "r"(a1u));
            const unsigned long long* brow =
                reinterpret_cast<const unsigned long long*>(&Bs[k][tn * 32]);
            #pragma unroll
            for (int p = 0; p < 16; p++) {
                unsigned long long b = brow[p];
                asm("fma.rn.f32x2 %0, %1, %2, %0;" : "+l"(acc[0][p]) : "l"(A0), "l"(b));
                asm("fma.rn.f32x2 %0, %1, %2, %0;" : "+l"(acc[1][p]) : "l"(A1), "l"(b));
            }
        }
        __syncthreads();
    }

    // ---- Epilogue: out[n][o][i][j]; lanes (tm) consecutive in pix -> coalesced ----
    #pragma unroll
    for (int mi = 0; mi < 2; mi++) {
        const int mm   = m0 + tm + 32 * mi;
        const int nimg = mm / PIX;
        const int px   = mm % PIX;
        float* ob = out + (size_t)nimg * (COUT * PIX) + px;
        #pragma unroll
        for (int p = 0; p < 16; p++) {
            unsigned int lo, hi;
            asm("mov.b64 {%0,%1}, %2;" : "=r"(lo), "=r"(hi) : "l"(acc[mi][p]));
            const int o = tn * 32 + 2 * p;
            ob[(size_t)o * PIX]       = __uint_as_float(lo);
            ob[(size_t)(o + 1) * PIX] = __uint_as_float(hi);
        }
    }
}

extern "C" void kernel_launch(void* const* d_in, const int* in_sizes, int n_in,
                              void* d_out, int out_size)
{
    const float* x      = (const float*)d_in[0];
    const float* bn_w   = (const float*)d_in[1];
    const float* bn_b   = (const float*)d_in[2];
    const float* bn_m   = (const float*)d_in[3];
    const float* bn_v   = (const float*)d_in[4];
    const float* conv_w = (const float*)d_in[5];
    float* out = (float*)d_out;

    const int grid = M_TOTAL / BM;   // 784
    transition_fused_kernel<<<grid, 256>>>(x, bn_w, bn_b, bn_m, bn_v, conv_w, out);
}